// round 12
// baseline (speedup 1.0000x reference)
#include <cuda_runtime.h>

#define BSZ   8
#define NMAX  64
#define NA    33600
#define BA    (BSZ * NA)          // 268800 (= 2100 * 128 exactly)
#define NPRO_ 31
#define NALP_ 24
#define NADS_ 37
#define ANCH  128                 // anchors per k_out block
#define THR   128                 // threads per k_out block

// ---------------- scratch (device globals; zero-initialized at load) -----
// g_cnt: claimant count per (b,anchor). g_enc: max over claimants of (64-g),
// so "first claimant" = 64 - g_enc; zero state = empty, no init kernel.
// k_out resets both to 0 after consuming (graph-replay safe).
__device__ int g_cnt[BA];
__device__ int g_enc[BA];

// pairwise IoU exactly as reference _pairwise_iou (union clamp 1e-6)
__device__ __forceinline__ float pair_iou(float gx1, float gy1, float gx2, float gy2,
                                          float ax1, float ay1, float ax2, float ay2) {
    float ga  = __fmul_rn(__fsub_rn(gx2, gx1), __fsub_rn(gy2, gy1));
    float aa  = __fmul_rn(__fsub_rn(ax2, ax1), __fsub_rn(ay2, ay1));
    float iw  = fmaxf(__fsub_rn(fminf(gx2, ax2), fmaxf(gx1, ax1)), 0.f);
    float ih  = fmaxf(__fsub_rn(fminf(gy2, ay2), fmaxf(gy1, ay1)), 0.f);
    float ovl = __fmul_rn(iw, ih);
    float uni = fmaxf(__fsub_rn(__fadd_rn(ga, aa), ovl), 1e-6f);
    return __fdiv_rn(ovl, uni);
}

// ---------------- per-GT assign: analytic 6x6 window per level -----------
// Anchors form a uniform grid per level: the 9 nearest grid points lie within
// 2.1213 cell units while anything outside the 6x6 window [floor(u)-2,
// floor(u)+3] is >= 2.99 away. Exact top-9 incl. the (dist_bits, index)
// tie-break matching jax.lax.top_k from just 36 candidates per level.
// One warp per (b,g); 8 warps per block. Lanes 0-2 each run their level's
// fully-unrolled 6x6 loop straight from global (all 36 loads in flight).
__global__ void __launch_bounds__(256) k_assign(const float* __restrict__ anc,
                                                const float* __restrict__ gtb,
                                                const float* __restrict__ mask_gt) {
    int w    = threadIdx.x >> 5;
    int lane = threadIdx.x & 31;
    int bg   = blockIdx.x * 8 + w;       // b*64 + g
    if (mask_gt[bg] <= 0.f) return;
    int b = bg >> 6;
    int g = bg & 63;

    const float* gt = gtb + bg * 4;
    float gx1 = gt[0], gy1 = gt[1], gx2 = gt[2], gy2 = gt[3];
    float gcx = __fmul_rn(__fadd_rn(gx1, gx2), 0.5f);
    float gcy = __fmul_rn(__fadd_rn(gy1, gy2), 0.5f);

    __shared__ int s_cand[8][27];

    if (lane < 3) {
        int   n     = (lane == 0) ? 160 : (lane == 1) ? 80 : 40;
        int   start = (lane == 0) ? 0   : (lane == 1) ? 25600 : 32000;
        float inv   = (lane == 0) ? 0.125f : (lane == 1) ? 0.0625f : 0.03125f;

        int ix0 = (int)floorf(gcx * inv - 0.5f) - 2;
        int iy0 = (int)floorf(gcy * inv - 0.5f) - 2;
        ix0 = min(max(ix0, 0), n - 6);
        iy0 = min(max(iy0, 0), n - 6);

        unsigned long long top[9];
#pragma unroll
        for (int j = 0; j < 9; j++) top[j] = ~0ull;

#pragma unroll
        for (int dy = 0; dy < 6; dy++) {
            int rowbase = start + (iy0 + dy) * n + ix0;
#pragma unroll
            for (int dx = 0; dx < 6; dx++) {
                int a = rowbase + dx;
                float4 ab = ((const float4*)anc)[a];
                float cx = __fmul_rn(__fadd_rn(ab.x, ab.z), 0.5f);
                float cy = __fmul_rn(__fadd_rn(ab.y, ab.w), 0.5f);
                float ddx = __fsub_rn(gcx, cx), ddy = __fsub_rn(gcy, cy);
                float d = __fsqrt_rn(__fadd_rn(__fmul_rn(ddx, ddx),
                                               __fmul_rn(ddy, ddy)));
                unsigned long long key =
                    ((unsigned long long)__float_as_uint(d) << 32) | (unsigned)a;
                if (key < top[8]) {
                    top[8] = key;
#pragma unroll
                    for (int j = 8; j > 0; --j) {
                        unsigned long long lo2 = top[j-1] < top[j] ? top[j-1] : top[j];
                        unsigned long long hi2 = top[j-1] < top[j] ? top[j]   : top[j-1];
                        top[j-1] = lo2; top[j] = hi2;
                    }
                }
            }
        }
#pragma unroll
        for (int r = 0; r < 9; r++)
            s_cand[w][lane * 9 + r] = (int)(unsigned)(top[r] & 0xffffffffull);
    }
    __syncwarp();

    // threshold over 27 candidates + positivity scatter (bit-exact reductions)
    {
        float ov = 0.f; int cand = 0; bool inside = false;
        if (lane < 27) {
            cand = s_cand[w][lane];
            float4 ab = ((const float4*)anc)[cand];
            ov = pair_iou(gx1, gy1, gx2, gy2, ab.x, ab.y, ab.z, ab.w);
            float acx = __fmul_rn(__fadd_rn(ab.x, ab.z), 0.5f);
            float acy = __fmul_rn(__fadd_rn(ab.y, ab.w), 0.5f);
            float mn = fminf(fminf(__fsub_rn(acx, gx1), __fsub_rn(acy, gy1)),
                             fminf(__fsub_rn(gx2, acx), __fsub_rn(gy2, acy)));
            inside = mn > 1e-9f;
        }
        float sred = ov;
#pragma unroll
        for (int o = 16; o; o >>= 1) sred = __fadd_rn(sred, __shfl_xor_sync(0xffffffffu, sred, o));
        float mean = __fdiv_rn(sred, 27.f);
        float dv = (lane < 27) ? __fsub_rn(ov, mean) : 0.f;
        float d2 = __fmul_rn(dv, dv);
#pragma unroll
        for (int o = 16; o; o >>= 1) d2 = __fadd_rn(d2, __shfl_xor_sync(0xffffffffu, d2, o));
        float thr = __fadd_rn(mean, __fsqrt_rn(__fdiv_rn(d2, 26.f)));

        if (lane < 27 && inside && ov > thr) {
            atomicAdd(&g_cnt[b * NA + cand], 1);
            atomicMax(&g_enc[b * NA + cand], 64 - g);
        }
    }
}

// ---- dense, 16B-aligned score-span writer (W = one-hot width) ----
// Span = ANCH anchors x W floats, written by THR threads as float4 quads.
// Hot positions: t0 = k0 - c0 and t1 = k1 + (W - c0). For fg anchors
// k < W so t0 < split = W - c0 and t1 >= split (>= 4 when non-crossing);
// for bg anchors k = 255 so neither t0 nor t1 can land in [0,4).
// Shared arrays padded to ANCH+1 for the branch-free dual-anchor read.
template<int W>
__device__ __forceinline__ void write_scores(float4* __restrict__ base4,
                                             const float* __restrict__ s_iou,
                                             const unsigned char* __restrict__ s_c,
                                             int tid) {
    const int NQ = (ANCH / 4) * W;         // quads per block span
    const int DA = (THR * 4) / W, DC = (THR * 4) - DA * W;
    int q  = tid;
    int p  = tid * 4;
    int a0 = p / W;
    int c0 = p - a0 * W;
    while (q < NQ) {
        float v0 = s_iou[a0],  v1 = s_iou[a0 + 1];
        int   k0 = s_c[a0],    k1 = s_c[a0 + 1];
        int t0 = k0 - c0;
        int t1 = k1 + (W - c0);
        float4 r;
        r.x = (0 == t0) ? v0 : ((0 == t1) ? v1 : 0.f);
        r.y = (1 == t0) ? v0 : ((1 == t1) ? v1 : 0.f);
        r.z = (2 == t0) ? v0 : ((2 == t1) ? v1 : 0.f);
        r.w = (3 == t0) ? v0 : ((3 == t1) ? v1 : 0.f);
        __stcs(&base4[q], r);
        q += THR; a0 += DA; c0 += DC;
        if (c0 >= W) { c0 -= W; a0++; }
    }
}

// ---------------- fused resolve + full output write ----------------------
// out layout (units of BA floats): [0,8) int targets | [8,12) bboxes |
// [12,20) corners | [20,51) pro | [51,75) alp | [75,297) ads | [297,298) fgb
__global__ void __launch_bounds__(THR) k_out(const float* __restrict__ anc,
                                             const float* __restrict__ gtb,
                                             const float* __restrict__ gtc,
                                             const float* __restrict__ gt_pro,
                                             const float* __restrict__ gt_alp,
                                             const float* __restrict__ gt_ads,
                                             const float* __restrict__ pdb,
                                             float* __restrict__ out) {
    const unsigned BAu = BA;
    int tid = threadIdx.x;
    unsigned idx = blockIdx.x * (unsigned)ANCH + tid;
    int b = idx / NA;
    int a = idx - b * NA;

    __shared__ float         s_gt[2][256];        // up to 2 batches' gt boxes
    __shared__ float         s_iou[ANCH + 1];     // +1 pad for dual-anchor reads
    __shared__ unsigned char s_cls[8][ANCH + 1];  // [section][anchor], padded

    // hoisted loads: issue the independent global reads up front (MLP)
    int cnt = g_cnt[idx];
    int enc = g_enc[idx];
    float4 pb = ((const float4*)pdb)[idx];

    int b0 = (blockIdx.x * ANCH) / NA;
    int b1 = (blockIdx.x * ANCH + (ANCH - 1)) / NA;
    for (int i = tid; i < 256; i += THR) {
        s_gt[0][i] = gtb[b0 * 256 + i];
        if (b1 != b0) s_gt[1][i] = gtb[b1 * 256 + i];
    }
    if (tid == 0) {
        s_iou[ANCH] = 0.f;
#pragma unroll
        for (int j = 0; j < 8; j++) s_cls[j][ANCH] = 255;
    }
    __syncthreads();
    const float* gp = s_gt[(b == b0) ? 0 : 1];

    // ---- phase 1: resolve (consume + reset scratch) ----
    g_cnt[idx] = 0;                 // self-reset for next replay
    g_enc[idx] = 0;

    int tgt = 0, fg = 0;
    if (cnt == 1) {
        tgt = 64 - enc;
        fg = 1;
    } else if (cnt > 1) {
        float4 ab = ((const float4*)anc)[a];
        float best = -1.f; int bi = 0;
        for (int g = 0; g < NMAX; g++) {
            float ov = pair_iou(gp[4*g], gp[4*g+1], gp[4*g+2], gp[4*g+3],
                                ab.x, ab.y, ab.z, ab.w);
            if (ov > best) { best = ov; bi = g; }
        }
        tgt = bi; fg = 1;
    }

    float iou = 0.f;
    if (fg) {
        // _batched_iou(gt, pd): clipped areas, +1e-9 denom
        float gx1 = gp[4*tgt], gy1 = gp[4*tgt+1], gx2 = gp[4*tgt+2], gy2 = gp[4*tgt+3];
        float a1 = __fmul_rn(fmaxf(__fsub_rn(gx2, gx1), 0.f), fmaxf(__fsub_rn(gy2, gy1), 0.f));
        float a2 = __fmul_rn(fmaxf(__fsub_rn(pb.z, pb.x), 0.f), fmaxf(__fsub_rn(pb.w, pb.y), 0.f));
        float iw = fmaxf(__fsub_rn(fminf(gx2, pb.z), fmaxf(gx1, pb.x)), 0.f);
        float ih = fmaxf(__fsub_rn(fminf(gy2, pb.w), fmaxf(gy1, pb.y)), 0.f);
        float ov = __fmul_rn(iw, ih);
        float den = __fadd_rn(__fsub_rn(__fadd_rn(a1, a2), ov), 1e-9f);
        iou = __fdiv_rn(ov, den);
    }
    s_iou[tid] = iou;

    int gi = b * NMAX + tgt;

    // dense class targets write the true sentinel (31/24/37) for bg, but
    // s_cls stores 255 for bg so score matching can never alias (the
    // sentinel W collides with the next anchor's class-0 slot otherwise).
    int cpro = fg ? (int)gt_pro[gi] : NPRO_;
    int calp = fg ? (int)gt_alp[gi] : NALP_;
    __stcs(&out[idx],       (float)cpro);
    __stcs(&out[BAu + idx], (float)calp);
    s_cls[0][tid] = fg ? (unsigned char)cpro : 255;
    s_cls[1][tid] = fg ? (unsigned char)calp : 255;
    const float* ad = gt_ads + gi * 6;
#pragma unroll
    for (int j = 0; j < 6; j++) {
        int c = fg ? (int)ad[j] : NADS_;
        __stcs(&out[(2 + j) * BAu + idx], (float)c);
        s_cls[2 + j][tid] = fg ? (unsigned char)c : 255;
    }

    // bboxes + corners + fgb (16B stores)
    __stcs(&((float4*)(out + 8u * BAu))[idx],          ((const float4*)gtb)[gi]);
    __stcs(&((float4*)(out + 12u * BAu))[idx * 2],     ((const float4*)gtc)[gi * 2]);
    __stcs(&((float4*)(out + 12u * BAu))[idx * 2 + 1], ((const float4*)gtc)[gi * 2 + 1]);
    __stcs(&out[297u * BAu + idx], fg ? 1.f : 0.f);

    __syncthreads();

    // ---- phase 2: dense 16B-aligned score spans ----
    unsigned A0 = blockIdx.x * (unsigned)ANCH;
    write_scores<31>((float4*)(out + 20u * BAu + A0 * 31u), s_iou, s_cls[0], tid);
    write_scores<24>((float4*)(out + 51u * BAu + A0 * 24u), s_iou, s_cls[1], tid);
#pragma unroll
    for (int j = 0; j < 6; j++)
        write_scores<37>((float4*)(out + (75u + 37u * j) * BAu + A0 * 37u),
                         s_iou, s_cls[2 + j], tid);
}

// ---------------- launch ----------------
extern "C" void kernel_launch(void* const* d_in, const int* in_sizes, int n_in,
                              void* d_out, int out_size) {
    const float *anc = nullptr, *pd = nullptr, *gtb = nullptr, *gtc = nullptr,
                *ads = nullptr, *pro = nullptr, *alp = nullptr, *msk = nullptr;
    int n512 = 0;
    for (int i = 0; i < n_in; i++) {
        int s = in_sizes[i];
        const float* p = (const float*)d_in[i];
        if      (s == 134400)  anc = p;       // anc_bboxes [33600,4]
        else if (s == 1075200) pd  = p;       // pd_bboxes  [8,33600,4]
        else if (s == 2048)    gtb = p;       // gt_bboxes  [8,64,4]
        else if (s == 4096)    gtc = p;       // gt_corners [8,64,8]
        else if (s == 3072)    ads = p;       // gt_ads     [8,64,6]
        else if (s == 512) {                  // gt_pro, gt_alp, mask_gt (in order)
            if (n512 == 0)      pro = p;
            else if (n512 == 1) alp = p;
            else                msk = p;
            n512++;
        }
    }
    float* out = (float*)d_out;

    k_assign<<<BSZ * NMAX / 8, 256>>>(anc, gtb, msk);
    k_out<<<BA / ANCH, THR>>>(anc, gtb, gtc, pro, alp, ads, pd, out);
}

// round 13
// speedup vs baseline: 1.0793x; 1.0793x over previous
#include <cuda_runtime.h>

#define BSZ   8
#define NMAX  64
#define NA    33600
#define BA    (BSZ * NA)          // 268800 (= 1050 * 256 exactly)
#define NPRO_ 31
#define NALP_ 24
#define NADS_ 37
#define ANCH  256                 // anchors per k_out block
#define THR   256                 // threads per k_out block

// ---------------- scratch (device globals; zero-initialized at load) -----
// g_cnt: claimant count per (b,anchor). g_enc: max over claimants of (64-g),
// so "first claimant" = 64 - g_enc; zero state = empty, no init kernel.
// k_out resets both to 0 after consuming (graph-replay safe).
__device__ int g_cnt[BA];
__device__ int g_enc[BA];

// pairwise IoU exactly as reference _pairwise_iou (union clamp 1e-6)
__device__ __forceinline__ float pair_iou(float gx1, float gy1, float gx2, float gy2,
                                          float ax1, float ay1, float ax2, float ay2) {
    float ga  = __fmul_rn(__fsub_rn(gx2, gx1), __fsub_rn(gy2, gy1));
    float aa  = __fmul_rn(__fsub_rn(ax2, ax1), __fsub_rn(ay2, ay1));
    float iw  = fmaxf(__fsub_rn(fminf(gx2, ax2), fmaxf(gx1, ax1)), 0.f);
    float ih  = fmaxf(__fsub_rn(fminf(gy2, ay2), fmaxf(gy1, ay1)), 0.f);
    float ovl = __fmul_rn(iw, ih);
    float uni = fmaxf(__fsub_rn(__fadd_rn(ga, aa), ovl), 1e-6f);
    return __fdiv_rn(ovl, uni);
}

// ---------------- per-GT assign: analytic 6x6 window per level -----------
// Anchors form a uniform grid per level: the 9 nearest grid points lie within
// 2.1213 cell units while anything outside the 6x6 window [floor(u)-2,
// floor(u)+3] is >= 2.99 away. Exact top-9 incl. the (dist_bits, index)
// tie-break matching jax.lax.top_k from just 36 candidates per level.
// ONE WARP PER (b,g), one warp per block: 512 tiny blocks spread across all
// 148 SMs (the 64x256 shape stacked 8 latency-serial warps on 64 SMs).
// Lanes 0-2 each run their level's fully-unrolled 6x6 loop straight from
// global (all 36 loads in flight).
__global__ void __launch_bounds__(32) k_assign(const float* __restrict__ anc,
                                               const float* __restrict__ gtb,
                                               const float* __restrict__ mask_gt) {
    int lane = threadIdx.x;
    int bg   = blockIdx.x;               // b*64 + g
    if (mask_gt[bg] <= 0.f) return;
    int b = bg >> 6;
    int g = bg & 63;

    const float* gt = gtb + bg * 4;
    float gx1 = gt[0], gy1 = gt[1], gx2 = gt[2], gy2 = gt[3];
    float gcx = __fmul_rn(__fadd_rn(gx1, gx2), 0.5f);
    float gcy = __fmul_rn(__fadd_rn(gy1, gy2), 0.5f);

    __shared__ int s_cand[27];

    if (lane < 3) {
        int   n     = (lane == 0) ? 160 : (lane == 1) ? 80 : 40;
        int   start = (lane == 0) ? 0   : (lane == 1) ? 25600 : 32000;
        float inv   = (lane == 0) ? 0.125f : (lane == 1) ? 0.0625f : 0.03125f;

        int ix0 = (int)floorf(gcx * inv - 0.5f) - 2;
        int iy0 = (int)floorf(gcy * inv - 0.5f) - 2;
        ix0 = min(max(ix0, 0), n - 6);
        iy0 = min(max(iy0, 0), n - 6);

        unsigned long long top[9];
#pragma unroll
        for (int j = 0; j < 9; j++) top[j] = ~0ull;

#pragma unroll
        for (int dy = 0; dy < 6; dy++) {
            int rowbase = start + (iy0 + dy) * n + ix0;
#pragma unroll
            for (int dx = 0; dx < 6; dx++) {
                int a = rowbase + dx;
                float4 ab = ((const float4*)anc)[a];
                float cx = __fmul_rn(__fadd_rn(ab.x, ab.z), 0.5f);
                float cy = __fmul_rn(__fadd_rn(ab.y, ab.w), 0.5f);
                float ddx = __fsub_rn(gcx, cx), ddy = __fsub_rn(gcy, cy);
                float d = __fsqrt_rn(__fadd_rn(__fmul_rn(ddx, ddx),
                                               __fmul_rn(ddy, ddy)));
                unsigned long long key =
                    ((unsigned long long)__float_as_uint(d) << 32) | (unsigned)a;
                if (key < top[8]) {
                    top[8] = key;
#pragma unroll
                    for (int j = 8; j > 0; --j) {
                        unsigned long long lo2 = top[j-1] < top[j] ? top[j-1] : top[j];
                        unsigned long long hi2 = top[j-1] < top[j] ? top[j]   : top[j-1];
                        top[j-1] = lo2; top[j] = hi2;
                    }
                }
            }
        }
#pragma unroll
        for (int r = 0; r < 9; r++)
            s_cand[lane * 9 + r] = (int)(unsigned)(top[r] & 0xffffffffull);
    }
    __syncwarp();

    // threshold over 27 candidates + positivity scatter (bit-exact reductions)
    {
        float ov = 0.f; int cand = 0; bool inside = false;
        if (lane < 27) {
            cand = s_cand[lane];
            float4 ab = ((const float4*)anc)[cand];
            ov = pair_iou(gx1, gy1, gx2, gy2, ab.x, ab.y, ab.z, ab.w);
            float acx = __fmul_rn(__fadd_rn(ab.x, ab.z), 0.5f);
            float acy = __fmul_rn(__fadd_rn(ab.y, ab.w), 0.5f);
            float mn = fminf(fminf(__fsub_rn(acx, gx1), __fsub_rn(acy, gy1)),
                             fminf(__fsub_rn(gx2, acx), __fsub_rn(gy2, acy)));
            inside = mn > 1e-9f;
        }
        float sred = ov;
#pragma unroll
        for (int o = 16; o; o >>= 1) sred = __fadd_rn(sred, __shfl_xor_sync(0xffffffffu, sred, o));
        float mean = __fdiv_rn(sred, 27.f);
        float dv = (lane < 27) ? __fsub_rn(ov, mean) : 0.f;
        float d2 = __fmul_rn(dv, dv);
#pragma unroll
        for (int o = 16; o; o >>= 1) d2 = __fadd_rn(d2, __shfl_xor_sync(0xffffffffu, d2, o));
        float thr = __fadd_rn(mean, __fsqrt_rn(__fdiv_rn(d2, 26.f)));

        if (lane < 27 && inside && ov > thr) {
            atomicAdd(&g_cnt[b * NA + cand], 1);
            atomicMax(&g_enc[b * NA + cand], 64 - g);
        }
    }
}

// ---- dense, 16B-aligned score-span writer (W = one-hot width) ----
// Span = ANCH anchors x W floats, written by THR threads as float4 quads.
// Hot positions: t0 = k0 - c0 and t1 = k1 + (W - c0). For fg anchors
// k < W so t0 < split = W - c0 and t1 >= split (>= 4 when non-crossing);
// for bg anchors k = 255 so neither t0 nor t1 can land in [0,4).
// Shared arrays padded to ANCH+1 for the branch-free dual-anchor read.
template<int W>
__device__ __forceinline__ void write_scores(float4* __restrict__ base4,
                                             const float* __restrict__ s_iou,
                                             const unsigned char* __restrict__ s_c,
                                             int tid) {
    const int NQ = (ANCH / 4) * W;         // quads per block span
    const int DA = (THR * 4) / W, DC = (THR * 4) - DA * W;
    int q  = tid;
    int p  = tid * 4;
    int a0 = p / W;
    int c0 = p - a0 * W;
    while (q < NQ) {
        float v0 = s_iou[a0],  v1 = s_iou[a0 + 1];
        int   k0 = s_c[a0],    k1 = s_c[a0 + 1];
        int t0 = k0 - c0;
        int t1 = k1 + (W - c0);
        float4 r;
        r.x = (0 == t0) ? v0 : ((0 == t1) ? v1 : 0.f);
        r.y = (1 == t0) ? v0 : ((1 == t1) ? v1 : 0.f);
        r.z = (2 == t0) ? v0 : ((2 == t1) ? v1 : 0.f);
        r.w = (3 == t0) ? v0 : ((3 == t1) ? v1 : 0.f);
        __stcs(&base4[q], r);
        q += THR; a0 += DA; c0 += DC;
        if (c0 >= W) { c0 -= W; a0++; }
    }
}

// ---------------- fused resolve + full output write ----------------------
// out layout (units of BA floats): [0,8) int targets | [8,12) bboxes |
// [12,20) corners | [20,51) pro | [51,75) alp | [75,297) ads | [297,298) fgb
__global__ void __launch_bounds__(THR) k_out(const float* __restrict__ anc,
                                             const float* __restrict__ gtb,
                                             const float* __restrict__ gtc,
                                             const float* __restrict__ gt_pro,
                                             const float* __restrict__ gt_alp,
                                             const float* __restrict__ gt_ads,
                                             const float* __restrict__ pdb,
                                             float* __restrict__ out) {
    const unsigned BAu = BA;
    int tid = threadIdx.x;
    unsigned idx = blockIdx.x * (unsigned)ANCH + tid;
    int b = idx / NA;
    int a = idx - b * NA;

    __shared__ float         s_gt[2][256];        // up to 2 batches' gt boxes
    __shared__ float         s_iou[ANCH + 1];     // +1 pad for dual-anchor reads
    __shared__ unsigned char s_cls[8][ANCH + 1];  // [section][anchor], padded

    // hoisted loads: issue the independent global reads up front (MLP)
    int cnt = g_cnt[idx];
    int enc = g_enc[idx];
    float4 pb = ((const float4*)pdb)[idx];

    int b0 = (blockIdx.x * ANCH) / NA;
    int b1 = (blockIdx.x * ANCH + (ANCH - 1)) / NA;
    s_gt[0][tid] = gtb[b0 * 256 + tid];
    if (b1 != b0) s_gt[1][tid] = gtb[b1 * 256 + tid];
    if (tid == 0) {
        s_iou[ANCH] = 0.f;
#pragma unroll
        for (int j = 0; j < 8; j++) s_cls[j][ANCH] = 255;
    }
    __syncthreads();
    const float* gp = s_gt[(b == b0) ? 0 : 1];

    // ---- phase 1: resolve (consume + reset scratch) ----
    g_cnt[idx] = 0;                 // self-reset for next replay
    g_enc[idx] = 0;

    int tgt = 0, fg = 0;
    if (cnt == 1) {
        tgt = 64 - enc;
        fg = 1;
    } else if (cnt > 1) {
        float4 ab = ((const float4*)anc)[a];
        float best = -1.f; int bi = 0;
        for (int g = 0; g < NMAX; g++) {
            float ov = pair_iou(gp[4*g], gp[4*g+1], gp[4*g+2], gp[4*g+3],
                                ab.x, ab.y, ab.z, ab.w);
            if (ov > best) { best = ov; bi = g; }
        }
        tgt = bi; fg = 1;
    }

    float iou = 0.f;
    if (fg) {
        // _batched_iou(gt, pd): clipped areas, +1e-9 denom
        float gx1 = gp[4*tgt], gy1 = gp[4*tgt+1], gx2 = gp[4*tgt+2], gy2 = gp[4*tgt+3];
        float a1 = __fmul_rn(fmaxf(__fsub_rn(gx2, gx1), 0.f), fmaxf(__fsub_rn(gy2, gy1), 0.f));
        float a2 = __fmul_rn(fmaxf(__fsub_rn(pb.z, pb.x), 0.f), fmaxf(__fsub_rn(pb.w, pb.y), 0.f));
        float iw = fmaxf(__fsub_rn(fminf(gx2, pb.z), fmaxf(gx1, pb.x)), 0.f);
        float ih = fmaxf(__fsub_rn(fminf(gy2, pb.w), fmaxf(gy1, pb.y)), 0.f);
        float ov = __fmul_rn(iw, ih);
        float den = __fadd_rn(__fsub_rn(__fadd_rn(a1, a2), ov), 1e-9f);
        iou = __fdiv_rn(ov, den);
    }
    s_iou[tid] = iou;

    int gi = b * NMAX + tgt;

    // dense class targets write the true sentinel (31/24/37) for bg, but
    // s_cls stores 255 for bg so score matching can never alias (the
    // sentinel W collides with the next anchor's class-0 slot otherwise).
    int cpro = fg ? (int)gt_pro[gi] : NPRO_;
    int calp = fg ? (int)gt_alp[gi] : NALP_;
    __stcs(&out[idx],       (float)cpro);
    __stcs(&out[BAu + idx], (float)calp);
    s_cls[0][tid] = fg ? (unsigned char)cpro : 255;
    s_cls[1][tid] = fg ? (unsigned char)calp : 255;
    const float* ad = gt_ads + gi * 6;
#pragma unroll
    for (int j = 0; j < 6; j++) {
        int c = fg ? (int)ad[j] : NADS_;
        __stcs(&out[(2 + j) * BAu + idx], (float)c);
        s_cls[2 + j][tid] = fg ? (unsigned char)c : 255;
    }

    // bboxes + corners + fgb (16B stores)
    __stcs(&((float4*)(out + 8u * BAu))[idx],          ((const float4*)gtb)[gi]);
    __stcs(&((float4*)(out + 12u * BAu))[idx * 2],     ((const float4*)gtc)[gi * 2]);
    __stcs(&((float4*)(out + 12u * BAu))[idx * 2 + 1], ((const float4*)gtc)[gi * 2 + 1]);
    __stcs(&out[297u * BAu + idx], fg ? 1.f : 0.f);

    __syncthreads();

    // ---- phase 2: dense 16B-aligned score spans ----
    unsigned A0 = blockIdx.x * (unsigned)ANCH;
    write_scores<31>((float4*)(out + 20u * BAu + A0 * 31u), s_iou, s_cls[0], tid);
    write_scores<24>((float4*)(out + 51u * BAu + A0 * 24u), s_iou, s_cls[1], tid);
#pragma unroll
    for (int j = 0; j < 6; j++)
        write_scores<37>((float4*)(out + (75u + 37u * j) * BAu + A0 * 37u),
                         s_iou, s_cls[2 + j], tid);
}

// ---------------- launch ----------------
extern "C" void kernel_launch(void* const* d_in, const int* in_sizes, int n_in,
                              void* d_out, int out_size) {
    const float *anc = nullptr, *pd = nullptr, *gtb = nullptr, *gtc = nullptr,
                *ads = nullptr, *pro = nullptr, *alp = nullptr, *msk = nullptr;
    int n512 = 0;
    for (int i = 0; i < n_in; i++) {
        int s = in_sizes[i];
        const float* p = (const float*)d_in[i];
        if      (s == 134400)  anc = p;       // anc_bboxes [33600,4]
        else if (s == 1075200) pd  = p;       // pd_bboxes  [8,33600,4]
        else if (s == 2048)    gtb = p;       // gt_bboxes  [8,64,4]
        else if (s == 4096)    gtc = p;       // gt_corners [8,64,8]
        else if (s == 3072)    ads = p;       // gt_ads     [8,64,6]
        else if (s == 512) {                  // gt_pro, gt_alp, mask_gt (in order)
            if (n512 == 0)      pro = p;
            else if (n512 == 1) alp = p;
            else                msk = p;
            n512++;
        }
    }
    float* out = (float*)d_out;

    k_assign<<<BSZ * NMAX, 32>>>(anc, gtb, msk);
    k_out<<<BA / ANCH, THR>>>(anc, gtb, gtc, pro, alp, ads, pd, out);
}

// round 14
// speedup vs baseline: 1.0901x; 1.0100x over previous
#include <cuda_runtime.h>

#define BSZ   8
#define NMAX  64
#define NA    33600
#define BA    (BSZ * NA)          // 268800 (= 1050 * 256 exactly)
#define NPRO_ 31
#define NALP_ 24
#define NADS_ 37
#define ANCH  256                 // anchors per k_out block
#define THR   256                 // threads per k_out block

// ---------------- scratch (device globals; zero-initialized at load) -----
// g_cnt: claimant count per (b,anchor). g_enc: max over claimants of (64-g),
// so "first claimant" = 64 - g_enc; zero state = empty, no init kernel.
// k_out resets both to 0 after consuming (graph-replay safe).
__device__ int g_cnt[BA];
__device__ int g_enc[BA];

// pairwise IoU exactly as reference _pairwise_iou (union clamp 1e-6)
__device__ __forceinline__ float pair_iou(float gx1, float gy1, float gx2, float gy2,
                                          float ax1, float ay1, float ax2, float ay2) {
    float ga  = __fmul_rn(__fsub_rn(gx2, gx1), __fsub_rn(gy2, gy1));
    float aa  = __fmul_rn(__fsub_rn(ax2, ax1), __fsub_rn(ay2, ay1));
    float iw  = fmaxf(__fsub_rn(fminf(gx2, ax2), fmaxf(gx1, ax1)), 0.f);
    float ih  = fmaxf(__fsub_rn(fminf(gy2, ay2), fmaxf(gy1, ay1)), 0.f);
    float ovl = __fmul_rn(iw, ih);
    float uni = fmaxf(__fsub_rn(__fadd_rn(ga, aa), ovl), 1e-6f);
    return __fdiv_rn(ovl, uni);
}

// ---------------- per-GT assign: analytic 6x6 window per level -----------
// Anchors form a uniform grid per level: the 9 nearest grid points lie within
// 2.1213 cell units while anything outside the 6x6 window [floor(u)-2,
// floor(u)+3] is >= 2.99 away. Exact top-9 incl. the (dist_bits, index)
// tie-break matching jax.lax.top_k from just 36 candidates per level.
// One warp per (b,g), one warp per block (512 tiny blocks across all SMs).
__global__ void __launch_bounds__(32) k_assign(const float* __restrict__ anc,
                                               const float* __restrict__ gtb,
                                               const float* __restrict__ mask_gt) {
    int lane = threadIdx.x;
    int bg   = blockIdx.x;               // b*64 + g
    if (mask_gt[bg] > 0.f) {
        int b = bg >> 6;
        int g = bg & 63;

        const float* gt = gtb + bg * 4;
        float gx1 = gt[0], gy1 = gt[1], gx2 = gt[2], gy2 = gt[3];
        float gcx = __fmul_rn(__fadd_rn(gx1, gx2), 0.5f);
        float gcy = __fmul_rn(__fadd_rn(gy1, gy2), 0.5f);

        __shared__ int s_cand[27];

        if (lane < 3) {
            int   n     = (lane == 0) ? 160 : (lane == 1) ? 80 : 40;
            int   start = (lane == 0) ? 0   : (lane == 1) ? 25600 : 32000;
            float inv   = (lane == 0) ? 0.125f : (lane == 1) ? 0.0625f : 0.03125f;

            int ix0 = (int)floorf(gcx * inv - 0.5f) - 2;
            int iy0 = (int)floorf(gcy * inv - 0.5f) - 2;
            ix0 = min(max(ix0, 0), n - 6);
            iy0 = min(max(iy0, 0), n - 6);

            unsigned long long top[9];
#pragma unroll
            for (int j = 0; j < 9; j++) top[j] = ~0ull;

#pragma unroll
            for (int dy = 0; dy < 6; dy++) {
                int rowbase = start + (iy0 + dy) * n + ix0;
#pragma unroll
                for (int dx = 0; dx < 6; dx++) {
                    int a = rowbase + dx;
                    float4 ab = ((const float4*)anc)[a];
                    float cx = __fmul_rn(__fadd_rn(ab.x, ab.z), 0.5f);
                    float cy = __fmul_rn(__fadd_rn(ab.y, ab.w), 0.5f);
                    float ddx = __fsub_rn(gcx, cx), ddy = __fsub_rn(gcy, cy);
                    float d = __fsqrt_rn(__fadd_rn(__fmul_rn(ddx, ddx),
                                                   __fmul_rn(ddy, ddy)));
                    unsigned long long key =
                        ((unsigned long long)__float_as_uint(d) << 32) | (unsigned)a;
                    if (key < top[8]) {
                        top[8] = key;
#pragma unroll
                        for (int j = 8; j > 0; --j) {
                            unsigned long long lo2 = top[j-1] < top[j] ? top[j-1] : top[j];
                            unsigned long long hi2 = top[j-1] < top[j] ? top[j]   : top[j-1];
                            top[j-1] = lo2; top[j] = hi2;
                        }
                    }
                }
            }
#pragma unroll
            for (int r = 0; r < 9; r++)
                s_cand[lane * 9 + r] = (int)(unsigned)(top[r] & 0xffffffffull);
        }
        __syncwarp();

        // threshold over 27 candidates + positivity scatter (bit-exact)
        float ov = 0.f; int cand = 0; bool inside = false;
        if (lane < 27) {
            cand = s_cand[lane];
            float4 ab = ((const float4*)anc)[cand];
            ov = pair_iou(gx1, gy1, gx2, gy2, ab.x, ab.y, ab.z, ab.w);
            float acx = __fmul_rn(__fadd_rn(ab.x, ab.z), 0.5f);
            float acy = __fmul_rn(__fadd_rn(ab.y, ab.w), 0.5f);
            float mn = fminf(fminf(__fsub_rn(acx, gx1), __fsub_rn(acy, gy1)),
                             fminf(__fsub_rn(gx2, acx), __fsub_rn(gy2, acy)));
            inside = mn > 1e-9f;
        }
        float sred = ov;
#pragma unroll
        for (int o = 16; o; o >>= 1) sred = __fadd_rn(sred, __shfl_xor_sync(0xffffffffu, sred, o));
        float mean = __fdiv_rn(sred, 27.f);
        float dv = (lane < 27) ? __fsub_rn(ov, mean) : 0.f;
        float d2 = __fmul_rn(dv, dv);
#pragma unroll
        for (int o = 16; o; o >>= 1) d2 = __fadd_rn(d2, __shfl_xor_sync(0xffffffffu, d2, o));
        float thr = __fadd_rn(mean, __fsqrt_rn(__fdiv_rn(d2, 26.f)));

        if (lane < 27 && inside && ov > thr) {
            atomicAdd(&g_cnt[b * NA + cand], 1);
            atomicMax(&g_enc[b * NA + cand], 64 - g);
        }
    }
#if __CUDA_ARCH__ >= 900
    cudaTriggerProgrammaticLaunchCompletion();
#endif
}

// ---- dense, 16B-aligned score-span writer (W = one-hot width) ----
// Span = ANCH anchors x W floats, written by THR threads as float4 quads.
// Hot positions: t0 = k0 - c0 and t1 = k1 + (W - c0). For fg anchors
// k < W so t0 < split = W - c0 and t1 >= split (>= 4 when non-crossing);
// for bg anchors k = 255 so neither t0 nor t1 can land in [0,4).
// Shared arrays padded to ANCH+1 for the branch-free dual-anchor read.
template<int W>
__device__ __forceinline__ void write_scores(float4* __restrict__ base4,
                                             const float* __restrict__ s_iou,
                                             const unsigned char* __restrict__ s_c,
                                             int tid) {
    const int NQ = (ANCH / 4) * W;         // quads per block span
    const int DA = (THR * 4) / W, DC = (THR * 4) - DA * W;
    int q  = tid;
    int p  = tid * 4;
    int a0 = p / W;
    int c0 = p - a0 * W;
    while (q < NQ) {
        float v0 = s_iou[a0],  v1 = s_iou[a0 + 1];
        int   k0 = s_c[a0],    k1 = s_c[a0 + 1];
        int t0 = k0 - c0;
        int t1 = k1 + (W - c0);
        float4 r;
        r.x = (0 == t0) ? v0 : ((0 == t1) ? v1 : 0.f);
        r.y = (1 == t0) ? v0 : ((1 == t1) ? v1 : 0.f);
        r.z = (2 == t0) ? v0 : ((2 == t1) ? v1 : 0.f);
        r.w = (3 == t0) ? v0 : ((3 == t1) ? v1 : 0.f);
        __stcs(&base4[q], r);
        q += THR; a0 += DA; c0 += DC;
        if (c0 >= W) { c0 -= W; a0++; }
    }
}

// ---------------- fused resolve + full output write ----------------------
// out layout (units of BA floats): [0,8) int targets | [8,12) bboxes |
// [12,20) corners | [20,51) pro | [51,75) alp | [75,297) ads | [297,298) fgb
// Launched with PDL: prologue (pdb load, s_gt fill) runs concurrently with
// k_assign; cudaGridDependencySynchronize() gates the g_cnt/g_enc reads.
__global__ void __launch_bounds__(THR) k_out(const float* __restrict__ anc,
                                             const float* __restrict__ gtb,
                                             const float* __restrict__ gtc,
                                             const float* __restrict__ gt_pro,
                                             const float* __restrict__ gt_alp,
                                             const float* __restrict__ gt_ads,
                                             const float* __restrict__ pdb,
                                             float* __restrict__ out) {
    const unsigned BAu = BA;
    int tid = threadIdx.x;
    unsigned idx = blockIdx.x * (unsigned)ANCH + tid;
    int b = idx / NA;
    int a = idx - b * NA;

    __shared__ float         s_gt[2][256];        // up to 2 batches' gt boxes
    __shared__ float         s_iou[ANCH + 1];     // +1 pad for dual-anchor reads
    __shared__ unsigned char s_cls[8][ANCH + 1];  // [section][anchor], padded

    // ---- prologue: independent of k_assign's output ----
    float4 pb = ((const float4*)pdb)[idx];

    int b0 = (blockIdx.x * ANCH) / NA;
    int b1 = (blockIdx.x * ANCH + (ANCH - 1)) / NA;
    s_gt[0][tid] = gtb[b0 * 256 + tid];
    if (b1 != b0) s_gt[1][tid] = gtb[b1 * 256 + tid];
    if (tid == 0) {
        s_iou[ANCH] = 0.f;
#pragma unroll
        for (int j = 0; j < 8; j++) s_cls[j][ANCH] = 255;
    }

    // ---- wait for k_assign's memory to be visible ----
#if __CUDA_ARCH__ >= 900
    cudaGridDependencySynchronize();
#endif

    // hoisted dependent loads
    int cnt = g_cnt[idx];
    int enc = g_enc[idx];
    __syncthreads();
    const float* gp = s_gt[(b == b0) ? 0 : 1];

    // ---- phase 1: resolve (consume + reset scratch) ----
    g_cnt[idx] = 0;                 // self-reset for next replay
    g_enc[idx] = 0;

    int tgt = 0, fg = 0;
    if (cnt == 1) {
        tgt = 64 - enc;
        fg = 1;
    } else if (cnt > 1) {
        float4 ab = ((const float4*)anc)[a];
        float best = -1.f; int bi = 0;
        for (int g = 0; g < NMAX; g++) {
            float ov = pair_iou(gp[4*g], gp[4*g+1], gp[4*g+2], gp[4*g+3],
                                ab.x, ab.y, ab.z, ab.w);
            if (ov > best) { best = ov; bi = g; }
        }
        tgt = bi; fg = 1;
    }

    float iou = 0.f;
    if (fg) {
        // _batched_iou(gt, pd): clipped areas, +1e-9 denom
        float gx1 = gp[4*tgt], gy1 = gp[4*tgt+1], gx2 = gp[4*tgt+2], gy2 = gp[4*tgt+3];
        float a1 = __fmul_rn(fmaxf(__fsub_rn(gx2, gx1), 0.f), fmaxf(__fsub_rn(gy2, gy1), 0.f));
        float a2 = __fmul_rn(fmaxf(__fsub_rn(pb.z, pb.x), 0.f), fmaxf(__fsub_rn(pb.w, pb.y), 0.f));
        float iw = fmaxf(__fsub_rn(fminf(gx2, pb.z), fmaxf(gx1, pb.x)), 0.f);
        float ih = fmaxf(__fsub_rn(fminf(gy2, pb.w), fmaxf(gy1, pb.y)), 0.f);
        float ov = __fmul_rn(iw, ih);
        float den = __fadd_rn(__fsub_rn(__fadd_rn(a1, a2), ov), 1e-9f);
        iou = __fdiv_rn(ov, den);
    }
    s_iou[tid] = iou;

    int gi = b * NMAX + tgt;

    // dense class targets write the true sentinel (31/24/37) for bg, but
    // s_cls stores 255 for bg so score matching can never alias (the
    // sentinel W collides with the next anchor's class-0 slot otherwise).
    int cpro = fg ? (int)gt_pro[gi] : NPRO_;
    int calp = fg ? (int)gt_alp[gi] : NALP_;
    __stcs(&out[idx],       (float)cpro);
    __stcs(&out[BAu + idx], (float)calp);
    s_cls[0][tid] = fg ? (unsigned char)cpro : 255;
    s_cls[1][tid] = fg ? (unsigned char)calp : 255;
    const float* ad = gt_ads + gi * 6;
#pragma unroll
    for (int j = 0; j < 6; j++) {
        int c = fg ? (int)ad[j] : NADS_;
        __stcs(&out[(2 + j) * BAu + idx], (float)c);
        s_cls[2 + j][tid] = fg ? (unsigned char)c : 255;
    }

    // bboxes + corners + fgb (16B stores)
    __stcs(&((float4*)(out + 8u * BAu))[idx],          ((const float4*)gtb)[gi]);
    __stcs(&((float4*)(out + 12u * BAu))[idx * 2],     ((const float4*)gtc)[gi * 2]);
    __stcs(&((float4*)(out + 12u * BAu))[idx * 2 + 1], ((const float4*)gtc)[gi * 2 + 1]);
    __stcs(&out[297u * BAu + idx], fg ? 1.f : 0.f);

    __syncthreads();

    // ---- phase 2: dense 16B-aligned score spans ----
    unsigned A0 = blockIdx.x * (unsigned)ANCH;
    write_scores<31>((float4*)(out + 20u * BAu + A0 * 31u), s_iou, s_cls[0], tid);
    write_scores<24>((float4*)(out + 51u * BAu + A0 * 24u), s_iou, s_cls[1], tid);
#pragma unroll
    for (int j = 0; j < 6; j++)
        write_scores<37>((float4*)(out + (75u + 37u * j) * BAu + A0 * 37u),
                         s_iou, s_cls[2 + j], tid);
}

// ---------------- launch ----------------
extern "C" void kernel_launch(void* const* d_in, const int* in_sizes, int n_in,
                              void* d_out, int out_size) {
    const float *anc = nullptr, *pd = nullptr, *gtb = nullptr, *gtc = nullptr,
                *ads = nullptr, *pro = nullptr, *alp = nullptr, *msk = nullptr;
    int n512 = 0;
    for (int i = 0; i < n_in; i++) {
        int s = in_sizes[i];
        const float* p = (const float*)d_in[i];
        if      (s == 134400)  anc = p;       // anc_bboxes [33600,4]
        else if (s == 1075200) pd  = p;       // pd_bboxes  [8,33600,4]
        else if (s == 2048)    gtb = p;       // gt_bboxes  [8,64,4]
        else if (s == 4096)    gtc = p;       // gt_corners [8,64,8]
        else if (s == 3072)    ads = p;       // gt_ads     [8,64,6]
        else if (s == 512) {                  // gt_pro, gt_alp, mask_gt (in order)
            if (n512 == 0)      pro = p;
            else if (n512 == 1) alp = p;
            else                msk = p;
            n512++;
        }
    }
    float* out = (float*)d_out;

    k_assign<<<BSZ * NMAX, 32>>>(anc, gtb, msk);

    // k_out with programmatic dependent launch: overlaps its launch ramp and
    // independent prologue with k_assign; griddepsync gates dependent reads.
    cudaLaunchConfig_t cfg = {};
    cfg.gridDim  = dim3(BA / ANCH, 1, 1);
    cfg.blockDim = dim3(THR, 1, 1);
    cfg.dynamicSmemBytes = 0;
    cfg.stream = 0;
    cudaLaunchAttribute attrs[1];
    attrs[0].id = cudaLaunchAttributeProgrammaticStreamSerialization;
    attrs[0].val.programmaticStreamSerializationAllowed = 1;
    cfg.attrs = attrs;
    cfg.numAttrs = 1;
    cudaLaunchKernelEx(&cfg, k_out, anc, gtb, gtc, pro, alp, ads, pd, out);
}